// round 14
// baseline (speedup 1.0000x reference)
#include <cuda_runtime.h>

#define N_NODES 16384
#define N_EDGES 262144
#define N_WIN   (N_EDGES / 32)

typedef unsigned long long ull;

// ---------------------------------------------------------------------------
// Static device scratch (no runtime allocation). NOTE: g_cnt is zero at module
// load and re-zeroed by down_kernel at the end of every launch sequence, so
// hist can run in the first kernel without a separate zeroing pass.
// ---------------------------------------------------------------------------
__device__ float  g_up[N_NODES * 128];     // [n][lane][4] = (s1, v1x, v1y, v1z)
__device__ float  g_acc[N_NODES * 256];    // interior-run node sums (written only where used)
__device__ float  g_stage0[N_WIN * 256];   // per-window first-run partial
__device__ float  g_stage1[N_WIN * 256];   // per-window final-run partial
__device__ int    g_cnt[N_NODES];
__device__ int    g_off[N_NODES];          // node range start (persist)
__device__ int    g_end[N_NODES];          // node range end   (persist)
__device__ int    g_cursor[N_NODES];       // mutable copy for scatter
__device__ int    g_base;
__device__ int2   g_shdr[N_EDGES];         // sorted header: (snd, rcv<<18 | e)
__device__ float2 g_pUp[1024];             // packed (W_up_s, W_up_v)
__device__ float4 g_pDn4[2048];            // packed (Wds[m][k], Wds[m][32+k], Wdv, Wdv)
__device__ float4 g_pSk[4096];             // packed skip weights per species

__device__ __forceinline__ float silu_f(float x) {
    return x / (1.0f + __expf(-x));
}

__device__ __forceinline__ ull pk2(float a, float b) {
    ull r; asm("mov.b64 %0, {%1,%2};" : "=l"(r) : "f"(a), "f"(b)); return r;
}
__device__ __forceinline__ void upk2(float& a, float& b, ull v) {
    asm("mov.b64 {%0,%1}, %2;" : "=f"(a), "=f"(b) : "l"(v));
}
__device__ __forceinline__ ull fma2_(ull a, ull b, ull c) {
    ull d; asm("fma.rn.f32x2 %0, %1, %2, %3;" : "=l"(d) : "l"(a), "l"(b), "l"(c)); return d;
}

// ---------------------------------------------------------------------------
// K1: weight packing (blocks 0..27) + receiver histogram (blocks 28..283,
// 4 edges per thread via int4).
// ---------------------------------------------------------------------------
__global__ void __launch_bounds__(256)
prep_hist_kernel(const float* __restrict__ Wus, const float* __restrict__ Wuv,
                 const float* __restrict__ Wds, const float* __restrict__ Wdv,
                 const float* __restrict__ Wss, const float* __restrict__ Wsv,
                 const int* __restrict__ rcv) {
    int b = blockIdx.x;
    if (b >= 28) {
        int i = (b - 28) * 256 + threadIdx.x;          // i in [0, 65536)
        int4 rr = ((const int4*)rcv)[i];
        atomicAdd(&g_cnt[rr.x], 1);
        atomicAdd(&g_cnt[rr.y], 1);
        atomicAdd(&g_cnt[rr.z], 1);
        atomicAdd(&g_cnt[rr.w], 1);
        return;
    }
    int t = b * 256 + threadIdx.x;
    if (t == 0) g_base = 0;
    if (t < 1024) g_pUp[t] = make_float2(Wus[t], Wuv[t]);
    int i = t - 1024;
    if (i >= 0 && i < 2048) {
        int m = i >> 5, k = i & 31;
        float wv = Wdv[i];
        g_pDn4[i] = make_float4(Wds[m * 64 + k], Wds[m * 64 + 32 + k], wv, wv);
    }
    int j = t - 3072;
    if (j >= 0 && j < 4096) {
        int sp = j >> 10, q = j & 1023, m = q >> 5, k = q & 31;
        g_pSk[j] = make_float4(Wss[sp * 2048 + m * 64 + k],
                               Wss[sp * 2048 + m * 64 + 32 + k],
                               Wsv[sp * 1024 + q], 0.f);
    }
}

// ---------------------------------------------------------------------------
// K2 parallel scan: block-local scan + atomic global base.
// Writes g_off / g_end (persistent) and g_cursor (scatter-mutable).
// ---------------------------------------------------------------------------
__global__ void __launch_bounds__(256) scan_kernel() {
    __shared__ int sWarp[8];
    __shared__ int sBase;
    int t = threadIdx.x;
    int lane = t & 31, warp = t >> 5;
    int n = blockIdx.x * 256 + t;
    int c = g_cnt[n];
    int incl = c;
    #pragma unroll
    for (int o = 1; o < 32; o <<= 1) {
        int v = __shfl_up_sync(0xffffffffu, incl, o);
        if (lane >= o) incl += v;
    }
    if (lane == 31) sWarp[warp] = incl;
    __syncthreads();
    if (t < 8) {
        int v = sWarp[t];
        #pragma unroll
        for (int o = 1; o < 8; o <<= 1) {
            int u = __shfl_up_sync(0xffu, v, o);
            if (t >= o) v += u;
        }
        sWarp[t] = v;
        if (t == 7) sBase = atomicAdd(&g_base, v);
    }
    __syncthreads();
    int warpBase = (warp > 0) ? sWarp[warp - 1] : 0;
    int o = sBase + warpBase + incl - c;
    g_off[n] = o;
    g_end[n] = o + c;
    g_cursor[n] = o;
}

// ---------------------------------------------------------------------------
// K3 fused: scatter 4 edges/thread (blocks 0..255) + up (256..2303).
// (No g_acc zeroing needed anymore.)
// ---------------------------------------------------------------------------
__global__ void __launch_bounds__(256)
mid_kernel(const float* __restrict__ nf,
           const int* __restrict__ receivers, const int* __restrict__ senders) {
    int b = blockIdx.x;
    int t = threadIdx.x;
    if (b < 256) {                                    // 8B-header scatter, x4
        int i = b * 256 + t;
        int4 rr = ((const int4*)receivers)[i];
        int4 ss = ((const int4*)senders)[i];
        int e0 = i * 4;
        int p0 = atomicAdd(&g_cursor[rr.x], 1);
        int p1 = atomicAdd(&g_cursor[rr.y], 1);
        int p2 = atomicAdd(&g_cursor[rr.z], 1);
        int p3 = atomicAdd(&g_cursor[rr.w], 1);
        g_shdr[p0] = make_int2(ss.x, (rr.x << 18) | e0);
        g_shdr[p1] = make_int2(ss.y, (rr.y << 18) | (e0 + 1));
        g_shdr[p2] = make_int2(ss.z, (rr.z << 18) | (e0 + 2));
        g_shdr[p3] = make_int2(ss.w, (rr.w << 18) | (e0 + 3));
        return;
    }
    // up-projection: 8 nodes per block (warp per node), packed weights
    __shared__ float2 sWu[1024];
    __shared__ float4 sF[8][32];
    for (int i = t; i < 1024; i += 256) sWu[i] = g_pUp[i];
    __syncthreads();
    int warp = t >> 5, lane = t & 31;
    int n = (b - 256) * 8 + warp;
    const float* f = nf + (size_t)n * 128;
    sF[warp][lane] = make_float4(f[lane], f[32 + 3 * lane],
                                 f[33 + 3 * lane], f[34 + 3 * lane]);
    __syncwarp();
    float os = 0.f, o0 = 0.f, o1 = 0.f, o2 = 0.f;
    #pragma unroll 8
    for (int m = 0; m < 32; m++) {
        float4 v = sF[warp][m];
        float2 w = sWu[m * 32 + lane];
        os = fmaf(v.x, w.x, os);
        o0 = fmaf(v.y, w.y, o0);
        o1 = fmaf(v.z, w.y, o1);
        o2 = fmaf(v.w, w.y, o2);
    }
    const float S = 0.17677669529663687f;
    ((float4*)g_up)[n * 32 + lane] = make_float4(os * S, o0 * S, o1 * S, o2 * S);
}

// ---------------------------------------------------------------------------
// K4 edge kernel (128 threads, 5 blocks/SM, ring depth 6). Warp = one 32-edge
// window. Flush policy (ALL plain ST.v4, zero atomics):
//   - first flush of window (run containing window head) -> g_stage0[w]
//   - final flush (run reaching window tail)             -> g_stage1[w]
//   - interior runs (complete, unique writer)            -> g_acc[node]
// ---------------------------------------------------------------------------
__global__ void __launch_bounds__(128, 5)
edge_kernel(const float* __restrict__ W_r1, const float* __restrict__ W_r2,
            const float* __restrict__ esh, const float* __restrict__ rad) {
    __shared__ float4 sHY[4][32];     // per warp: (unused, y0, y1, y2) per edge
    __shared__ ull    sHp[4][128];    // per warp: h pairs, 4 ull per edge
    int t = threadIdx.x, warp = t >> 5, lane = t & 31;
    int w = blockIdx.x * 4 + warp;    // window id
    int p0 = w * 32;

    const float INV_SQRT8 = 0.3535533905932738f;
    const float SC = INV_SQRT8 * 0.25f;          // radial scale * AVG_NEIGH^-0.5
    const float INV_SQRT3 = 0.5773502691896258f;

    // wp[p][c] = (W2[2p][c*32+lane], W2[2p+1][c*32+lane]) * scale_c
    ull wp[4][4];
    #pragma unroll
    for (int p = 0; p < 4; p++) {
        #pragma unroll
        for (int c = 0; c < 4; c++) {
            float scc = (c == 3) ? SC * INV_SQRT3 : SC;
            wp[p][c] = pk2(__ldg(&W_r2[(2 * p) * 128 + c * 32 + lane]) * scc,
                           __ldg(&W_r2[(2 * p + 1) * 128 + c * 32 + lane]) * scc);
        }
    }
    // W1 columns for this lane's j-pair (j = 2j', 2j'+1 with j' = lane&3)
    int j2 = (lane & 3) * 2;
    float W1a[8], W1b[8];
    #pragma unroll
    for (int k = 0; k < 8; k++) {
        W1a[k] = __ldg(&W_r1[k * 8 + j2]);
        W1b[k] = __ldg(&W_r1[k * 8 + j2 + 1]);
    }

    // full-warp header load (32 edges), then gather each edge's sh + radial
    int2 hdr = g_shdr[p0 + lane];
    int e = hdr.y & 0x3FFFF;
    float4 shq = __ldg(&((const float4*)esh)[e]);
    float4 rq0 = __ldg(&((const float4*)rad)[e * 2]);
    float4 rq1 = __ldg(&((const float4*)rad)[e * 2 + 1]);
    sHY[warp][lane] = make_float4(0.f, shq.y, shq.z, shq.w);

    // run-boundary ballot (uniform across warp)
    int r = (int)(((unsigned)hdr.y) >> 18);
    int rprev = __shfl_up_sync(0xffffffffu, r, 1);
    unsigned bnd = __ballot_sync(0xffffffffu, (lane > 0) && (r != rprev));

    // batched radial MLP: 4 batches x 8 edges; lane = (e_loc = lane>>2, j' = lane&3)
    int el = lane >> 2;
    #pragma unroll
    for (int b = 0; b < 4; b++) {
        int src = b * 8 + el;
        float rk, preA, preB;
        rk = __shfl_sync(0xffffffffu, rq0.x, src); preA = rk * W1a[0]; preB = rk * W1b[0];
        rk = __shfl_sync(0xffffffffu, rq0.y, src); preA = fmaf(rk, W1a[1], preA); preB = fmaf(rk, W1b[1], preB);
        rk = __shfl_sync(0xffffffffu, rq0.z, src); preA = fmaf(rk, W1a[2], preA); preB = fmaf(rk, W1b[2], preB);
        rk = __shfl_sync(0xffffffffu, rq0.w, src); preA = fmaf(rk, W1a[3], preA); preB = fmaf(rk, W1b[3], preB);
        rk = __shfl_sync(0xffffffffu, rq1.x, src); preA = fmaf(rk, W1a[4], preA); preB = fmaf(rk, W1b[4], preB);
        rk = __shfl_sync(0xffffffffu, rq1.y, src); preA = fmaf(rk, W1a[5], preA); preB = fmaf(rk, W1b[5], preB);
        rk = __shfl_sync(0xffffffffu, rq1.z, src); preA = fmaf(rk, W1a[6], preA); preB = fmaf(rk, W1b[6], preB);
        rk = __shfl_sync(0xffffffffu, rq1.w, src); preA = fmaf(rk, W1a[7], preA); preB = fmaf(rk, W1b[7], preB);
        float hA = silu_f(preA * INV_SQRT8);
        float hB = silu_f(preB * INV_SQRT8);
        sHp[warp][b * 32 + lane] = pk2(hA, hB);   // slot = E*4 + j'
    }
    __syncwarp();

    // prime the 6-deep sender-gather ring (MLP=6)
    const float4* upL = (const float4*)g_up + lane;
    float4 ring[6];
    #pragma unroll
    for (int q = 0; q < 6; q++) {
        int snd = __shfl_sync(0xffffffffu, hdr.x, q);
        ring[q] = __ldg(&upL[snd * 32]);
    }

    float aS0 = 0.f, aS1 = 0.f;
    float aV0l = 0.f, aV0h = 0.f, aV1l = 0.f, aV1h = 0.f, aV2l = 0.f, aV2h = 0.f;
    int nflush = 0;

    auto storeTo = [&](float* dst) {
        asm volatile("st.global.v4.f32 [%0], {%1,%2,%3,%4};"
                     :: "l"(dst), "f"(aS0), "f"(aS1), "f"(aV0l), "f"(aV0h) : "memory");
        asm volatile("st.global.v4.f32 [%0], {%1,%2,%3,%4};"
                     :: "l"(dst + 4), "f"(aV1l), "f"(aV1h), "f"(aV2l), "f"(aV2h) : "memory");
    };

    const ulonglong2* hp2 = (const ulonglong2*)sHp[warp];

    #pragma unroll
    for (int i = 0; i < 32; i++) {
        if (i > 0 && ((bnd >> i) & 1u)) {
            float* dst;
            if (nflush == 0) {
                dst = g_stage0 + (size_t)w * 256 + lane * 8;      // first run of window
            } else {
                int node = __shfl_sync(0xffffffffu, r, i - 1);    // interior (complete) run
                dst = g_acc + (size_t)node * 256 + lane * 8;
            }
            storeTo(dst);
            nflush++;
            aS0 = aS1 = aV0l = aV0h = aV1l = aV1h = aV2l = aV2h = 0.f;
        }
        float4 u = ring[i % 6];
        if (i < 26) {                     // refill ring with edge i+6's gather
            int snd = __shfl_sync(0xffffffffu, hdr.x, i + 6);
            ring[i % 6] = __ldg(&upL[snd * 32]);
        }
        float4 hy = sHY[warp][i];                    // uniform LDS.128 (y0,y1,y2)
        ulonglong2 v1 = hp2[i * 2];                  // h pairs (0,1),(2,3)
        ulonglong2 v2 = hp2[i * 2 + 1];              // h pairs (4,5),(6,7)

        ull a0 = 0, a1 = 0, a2 = 0, a3 = 0;          // 4 independent chains, depth 4
        a0 = fma2_(v1.x, wp[0][0], a0); a1 = fma2_(v1.x, wp[0][1], a1);
        a2 = fma2_(v1.x, wp[0][2], a2); a3 = fma2_(v1.x, wp[0][3], a3);
        a0 = fma2_(v1.y, wp[1][0], a0); a1 = fma2_(v1.y, wp[1][1], a1);
        a2 = fma2_(v1.y, wp[1][2], a2); a3 = fma2_(v1.y, wp[1][3], a3);
        a0 = fma2_(v2.x, wp[2][0], a0); a1 = fma2_(v2.x, wp[2][1], a1);
        a2 = fma2_(v2.x, wp[2][2], a2); a3 = fma2_(v2.x, wp[2][3], a3);
        a0 = fma2_(v2.y, wp[3][0], a0); a1 = fma2_(v2.y, wp[3][1], a1);
        a2 = fma2_(v2.y, wp[3][2], a2); a3 = fma2_(v2.y, wp[3][3], a3);

        float w0, w1, w2, w3, lo, hi;
        upk2(lo, hi, a0); w0 = lo + hi;
        upk2(lo, hi, a1); w1 = lo + hi;
        upk2(lo, hi, a2); w2 = lo + hi;
        upk2(lo, hi, a3); w3 = lo + hi;

        float dot = u.y * hy.y;
        dot = fmaf(u.z, hy.z, dot);
        dot = fmaf(u.w, hy.w, dot);
        float sst = u.x * w2;

        aS0  = fmaf(u.x, w0, aS0);
        aS1  = fmaf(dot, w3, aS1);
        aV0l = fmaf(u.y, w1, aV0l);  aV0h = fmaf(sst, hy.y, aV0h);
        aV1l = fmaf(u.z, w1, aV1l);  aV1h = fmaf(sst, hy.z, aV1h);
        aV2l = fmaf(u.w, w1, aV2l);  aV2h = fmaf(sst, hy.w, aV2h);
    }
    storeTo(g_stage1 + (size_t)w * 256 + lane * 8);   // final run of window
}

// ---------------------------------------------------------------------------
// K5 down-projection + skip + gating. Reconstructs node sums from
// {stage0, stage1, g_acc} via the single-writer slot rule. 4 nodes per warp,
// __ldg packed weights, f32x2 accumulation. Re-zeroes g_cnt for next call.
// ---------------------------------------------------------------------------
__global__ void __launch_bounds__(128)
down_kernel(const float* __restrict__ nf,
            const int* __restrict__ species,
            float* __restrict__ out) {
    __shared__ float4 st[4][4][96];   // [warp][node][0:64 columns | 64:96 nf]
    int t = threadIdx.x, warp = t >> 5, lane = t & 31;
    int gid = blockIdx.x * 128 + t;
    if (gid < N_NODES) g_cnt[gid] = 0;     // restore invariant for next call
    int n0 = blockIdx.x * 16 + warp * 4;

    #pragma unroll
    for (int u = 0; u < 4; u++) {
        int n = n0 + u;
        int off = g_off[n], end = g_end[n];
        float4 qa = make_float4(0.f, 0.f, 0.f, 0.f);
        float4 qb = qa;
        if (end > off) {
            int wA = off >> 5, wB = (end - 1) >> 5;
            for (int w = wA; w <= wB; w++) {
                const float* src;
                if (end >= (w + 1) * 32)          // run reaches window tail
                    src = g_stage1 + (size_t)w * 256;
                else if (off <= w * 32)           // run starts at window head
                    src = g_stage0 + (size_t)w * 256;
                else                              // interior run (unique)
                    src = g_acc + (size_t)n * 256;
                const float4* p4 = (const float4*)src;
                float4 a = __ldg(&p4[lane * 2]);
                float4 b = __ldg(&p4[lane * 2 + 1]);
                qa.x += a.x; qa.y += a.y; qa.z += a.z; qa.w += a.w;
                qb.x += b.x; qb.y += b.y; qb.z += b.z; qb.w += b.w;
            }
        }
        st[warp][u][lane]      = make_float4(qa.x, qa.z, qb.x, qb.z);  // cols m=lane
        st[warp][u][32 + lane] = make_float4(qa.y, qa.w, qb.y, qb.w);  // cols m=32+lane
        const float* f = nf + (size_t)n * 128;
        st[warp][u][64 + lane] = make_float4(f[lane], f[32 + 3 * lane],
                                             f[33 + 3 * lane], f[34 + 3 * lane]);
    }
    __syncwarp();

    const ulonglong2* wdn = (const ulonglong2*)g_pDn4;   // (w2-pair, wv2-pair)
    ull g01[4] = {0, 0, 0, 0}, gv[4] = {0, 0, 0, 0};
    float g4[4] = {0.f, 0.f, 0.f, 0.f};
    #pragma unroll 4
    for (int m = 0; m < 64; m++) {
        ulonglong2 wd = __ldg(&wdn[m * 32 + lane]);
        float wv, dummy;
        upk2(wv, dummy, wd.y);
        #pragma unroll
        for (int u = 0; u < 4; u++) {
            float4 b = st[warp][u][m];
            g01[u] = fma2_(pk2(b.x, b.x), wd.x, g01[u]);
            gv[u]  = fma2_(pk2(b.y, b.z), wd.y, gv[u]);
            g4[u]  = fmaf(b.w, wv, g4[u]);
        }
    }

    int sp[4];
    #pragma unroll
    for (int u = 0; u < 4; u++) sp[u] = species[n0 + u];

    ull s01[4] = {0, 0, 0, 0}, sv[4] = {0, 0, 0, 0};
    float s4[4] = {0.f, 0.f, 0.f, 0.f};
    #pragma unroll 4
    for (int m = 0; m < 32; m++) {
        #pragma unroll
        for (int u = 0; u < 4; u++) {
            float4 w = __ldg(&g_pSk[sp[u] * 1024 + m * 32 + lane]);
            float4 c = st[warp][u][64 + m];
            s01[u] = fma2_(pk2(c.x, c.x), pk2(w.x, w.y), s01[u]);
            sv[u]  = fma2_(pk2(c.y, c.z), pk2(w.z, w.z), sv[u]);
            s4[u]  = fmaf(c.w, w.z, s4[u]);
        }
    }

    const float A = 0.5f * 0.125f;                 // 0.5 * (2*MUL)^-0.5
    const float B = 0.5f * 0.17677669529663687f;   // 0.5 * MUL^-0.5

    #pragma unroll
    for (int u = 0; u < 4; u++) {
        float G0, G1, H0, H1, S0, S1, T0, T1;
        upk2(G0, G1, g01[u]);
        upk2(H0, H1, gv[u]);
        upk2(S0, S1, s01[u]);
        upk2(T0, T1, sv[u]);
        G0 = G0 * A + S0 * B;
        G1 = G1 * A + S1 * B;
        H0 = H0 * A + T0 * B;
        H1 = H1 * A + T1 * B;
        float H2 = g4[u] * A + s4[u] * B;
        float feat = silu_f(G0);
        float gate = silu_f(G1);
        float* o = out + (size_t)(n0 + u) * 128;
        o[lane] = feat;
        o[32 + lane * 3 + 0] = H0 * gate;
        o[32 + lane * 3 + 1] = H1 * gate;
        o[32 + lane * 3 + 2] = H2 * gate;
    }
}

// ---------------------------------------------------------------------------
extern "C" void kernel_launch(void* const* d_in, const int* in_sizes, int n_in,
                              void* d_out, int out_size) {
    const float* nf  = (const float*)d_in[0];
    const float* esh = (const float*)d_in[1];
    const float* rad = (const float*)d_in[2];
    const float* Wus = (const float*)d_in[3];
    const float* Wuv = (const float*)d_in[4];
    const float* Wr1 = (const float*)d_in[5];
    const float* Wr2 = (const float*)d_in[6];
    const float* Wds = (const float*)d_in[7];
    const float* Wdv = (const float*)d_in[8];
    const float* Wss = (const float*)d_in[9];
    const float* Wsv = (const float*)d_in[10];
    const int* snd  = (const int*)d_in[11];
    const int* rcv  = (const int*)d_in[12];
    const int* spec = (const int*)d_in[13];
    float* out = (float*)d_out;

    prep_hist_kernel<<<284, 256>>>(Wus, Wuv, Wds, Wdv, Wss, Wsv, rcv);
    scan_kernel<<<64, 256>>>();
    mid_kernel<<<2304, 256>>>(nf, rcv, snd);
    edge_kernel<<<2048, 128>>>(Wr1, Wr2, esh, rad);
    down_kernel<<<1024, 128>>>(nf, spec, out);
}

// round 15
// speedup vs baseline: 1.0237x; 1.0237x over previous
#include <cuda_runtime.h>

#define N_NODES 16384
#define N_EDGES 262144

typedef unsigned long long ull;

// ---------------------------------------------------------------------------
// Static device scratch (no runtime allocation). NOTE: g_cnt is zero at module
// load and re-zeroed by down_kernel at the end of every launch sequence, so
// hist can run in the first kernel without a separate zeroing pass.
// ---------------------------------------------------------------------------
__device__ float  g_up[N_NODES * 128];     // [n][lane][4] = (s1, v1x, v1y, v1z)
__device__ float  g_acc[N_NODES * 256];    // [n][lane][8] = (S0,S1,V0l,V0h,V1l,V1h,V2l,V2h)
__device__ int    g_cnt[N_NODES];
__device__ int    g_cursor[N_NODES];
__device__ int    g_base;
__device__ int2   g_shdr[N_EDGES];         // sorted header: (snd, rcv<<18 | e)
__device__ float4 g_pDn4[2048];            // packed (Wds[m][k], Wds[m][32+k], Wdv, Wdv)
__device__ float4 g_pSk[4096];             // packed skip weights per species

__device__ __forceinline__ float silu_f(float x) {
    return x / (1.0f + __expf(-x));
}

__device__ __forceinline__ ull pk2(float a, float b) {
    ull r; asm("mov.b64 %0, {%1,%2};" : "=l"(r) : "f"(a), "f"(b)); return r;
}
__device__ __forceinline__ void upk2(float& a, float& b, ull v) {
    asm("mov.b64 {%0,%1}, %2;" : "=f"(a), "=f"(b) : "l"(v));
}
__device__ __forceinline__ ull fma2_(ull a, ull b, ull c) {
    ull d; asm("fma.rn.f32x2 %0, %1, %2, %3;" : "=l"(d) : "l"(a), "l"(b), "l"(c)); return d;
}

// ---------------------------------------------------------------------------
// K1 fused: weight packing (blocks 0..27) + receiver histogram (28..283,
// 4 edges/thread) + up-projection (284..2331). Hist atomic latency hides
// under up's compute — all three are mutually independent.
// ---------------------------------------------------------------------------
__global__ void __launch_bounds__(256)
prep_kernel(const float* __restrict__ nf,
            const float* __restrict__ Wus, const float* __restrict__ Wuv,
            const float* __restrict__ Wds, const float* __restrict__ Wdv,
            const float* __restrict__ Wss, const float* __restrict__ Wsv,
            const int* __restrict__ rcv) {
    int b = blockIdx.x;
    int t = threadIdx.x;
    if (b < 28) {                                     // pack down/skip weights
        int g = b * 256 + t;
        if (g == 0) g_base = 0;
        int i = g - 1024;
        if (i >= 0 && i < 2048) {
            int m = i >> 5, k = i & 31;
            float wv = Wdv[i];
            g_pDn4[i] = make_float4(Wds[m * 64 + k], Wds[m * 64 + 32 + k], wv, wv);
        }
        int j = g - 3072;
        if (j >= 0 && j < 4096) {
            int sp = j >> 10, q = j & 1023, m = q >> 5, k = q & 31;
            g_pSk[j] = make_float4(Wss[sp * 2048 + m * 64 + k],
                                   Wss[sp * 2048 + m * 64 + 32 + k],
                                   Wsv[sp * 1024 + q], 0.f);
        }
        return;
    }
    if (b < 284) {                                    // receiver histogram x4
        int i = (b - 28) * 256 + t;                   // i in [0, 65536)
        int4 rr = ((const int4*)rcv)[i];
        atomicAdd(&g_cnt[rr.x], 1);
        atomicAdd(&g_cnt[rr.y], 1);
        atomicAdd(&g_cnt[rr.z], 1);
        atomicAdd(&g_cnt[rr.w], 1);
        return;
    }
    // up-projection: 8 nodes per block (warp per node); raw weights -> SMEM
    __shared__ float2 sWu[1024];
    __shared__ float4 sF[8][32];
    for (int i = t; i < 1024; i += 256) sWu[i] = make_float2(Wus[i], Wuv[i]);
    __syncthreads();
    int warp = t >> 5, lane = t & 31;
    int n = (b - 284) * 8 + warp;
    const float* f = nf + (size_t)n * 128;
    sF[warp][lane] = make_float4(f[lane], f[32 + 3 * lane],
                                 f[33 + 3 * lane], f[34 + 3 * lane]);
    __syncwarp();
    float os = 0.f, o0 = 0.f, o1 = 0.f, o2 = 0.f;
    #pragma unroll 8
    for (int m = 0; m < 32; m++) {
        float4 v = sF[warp][m];
        float2 w = sWu[m * 32 + lane];
        os = fmaf(v.x, w.x, os);
        o0 = fmaf(v.y, w.y, o0);
        o1 = fmaf(v.z, w.y, o1);
        o2 = fmaf(v.w, w.y, o2);
    }
    const float S = 0.17677669529663687f;
    ((float4*)g_up)[n * 32 + lane] = make_float4(os * S, o0 * S, o1 * S, o2 * S);
}

// ---------------------------------------------------------------------------
// K2 parallel scan: block-local scan + atomic global base
// ---------------------------------------------------------------------------
__global__ void __launch_bounds__(256) scan_kernel() {
    __shared__ int sWarp[8];
    __shared__ int sBase;
    int t = threadIdx.x;
    int lane = t & 31, warp = t >> 5;
    int n = blockIdx.x * 256 + t;
    int c = g_cnt[n];
    int incl = c;
    #pragma unroll
    for (int o = 1; o < 32; o <<= 1) {
        int v = __shfl_up_sync(0xffffffffu, incl, o);
        if (lane >= o) incl += v;
    }
    if (lane == 31) sWarp[warp] = incl;
    __syncthreads();
    if (t < 8) {
        int v = sWarp[t];
        #pragma unroll
        for (int o = 1; o < 8; o <<= 1) {
            int u = __shfl_up_sync(0xffu, v, o);
            if (t >= o) v += u;
        }
        sWarp[t] = v;
        if (t == 7) sBase = atomicAdd(&g_base, v);
    }
    __syncthreads();
    int warpBase = (warp > 0) ? sWarp[warp - 1] : 0;
    g_cursor[n] = sBase + warpBase + incl - c;
}

// ---------------------------------------------------------------------------
// K3 fused: scatter 4 edges/thread (blocks 0..255) + zero_acc (256..4351).
// Zeroing (bandwidth-bound) overlaps the scatter's atomic latency chains.
// ---------------------------------------------------------------------------
__global__ void __launch_bounds__(256)
mid_kernel(const int* __restrict__ receivers, const int* __restrict__ senders) {
    int b = blockIdx.x;
    int t = threadIdx.x;
    if (b < 256) {                                    // 8B-header scatter, x4
        int i = b * 256 + t;
        int4 rr = ((const int4*)receivers)[i];
        int4 ss = ((const int4*)senders)[i];
        int e0 = i * 4;
        int p0 = atomicAdd(&g_cursor[rr.x], 1);
        int p1 = atomicAdd(&g_cursor[rr.y], 1);
        int p2 = atomicAdd(&g_cursor[rr.z], 1);
        int p3 = atomicAdd(&g_cursor[rr.w], 1);
        g_shdr[p0] = make_int2(ss.x, (rr.x << 18) | e0);
        g_shdr[p1] = make_int2(ss.y, (rr.y << 18) | (e0 + 1));
        g_shdr[p2] = make_int2(ss.z, (rr.z << 18) | (e0 + 2));
        g_shdr[p3] = make_int2(ss.w, (rr.w << 18) | (e0 + 3));
        return;
    }
    ((float4*)g_acc)[(b - 256) * 256 + t] = make_float4(0.f, 0.f, 0.f, 0.f);
}

// ---------------------------------------------------------------------------
// K4 edge kernel (round-13 proven config: 128 threads, 5 blocks/SM, ring 6).
// Warp handles 32 receiver-sorted edges. MLP computes 2 h-values/lane, stores
// pre-packed pairs (STS.64); inner loop: 2 uniform LDS.128 for h, 1 for y;
// pair-dot matvec (4 independent fma2 chains of depth 4); 6-deep register
// prefetch ring (SHFL refill). Ballot run boundaries; ST interior runs,
// RED window-straddling first/last runs (g_acc pre-zeroed).
// ---------------------------------------------------------------------------
__global__ void __launch_bounds__(128, 5)
edge_kernel(const float* __restrict__ W_r1, const float* __restrict__ W_r2,
            const float* __restrict__ esh, const float* __restrict__ rad) {
    __shared__ float4 sHY[4][32];     // per warp: (unused, y0, y1, y2) per edge
    __shared__ ull    sHp[4][128];    // per warp: h pairs, 4 ull per edge
    int t = threadIdx.x, warp = t >> 5, lane = t & 31;
    int p0 = (blockIdx.x * 4 + warp) * 32;

    const float INV_SQRT8 = 0.3535533905932738f;
    const float SC = INV_SQRT8 * 0.25f;          // radial scale * AVG_NEIGH^-0.5
    const float INV_SQRT3 = 0.5773502691896258f;

    // wp[p][c] = (W2[2p][c*32+lane], W2[2p+1][c*32+lane]) * scale_c
    ull wp[4][4];
    #pragma unroll
    for (int p = 0; p < 4; p++) {
        #pragma unroll
        for (int c = 0; c < 4; c++) {
            float scc = (c == 3) ? SC * INV_SQRT3 : SC;
            wp[p][c] = pk2(__ldg(&W_r2[(2 * p) * 128 + c * 32 + lane]) * scc,
                           __ldg(&W_r2[(2 * p + 1) * 128 + c * 32 + lane]) * scc);
        }
    }
    // W1 columns for this lane's j-pair (j = 2j', 2j'+1 with j' = lane&3)
    int j2 = (lane & 3) * 2;
    float W1a[8], W1b[8];
    #pragma unroll
    for (int k = 0; k < 8; k++) {
        W1a[k] = __ldg(&W_r1[k * 8 + j2]);
        W1b[k] = __ldg(&W_r1[k * 8 + j2 + 1]);
    }

    // full-warp header load (32 edges), then gather each edge's sh + radial
    int2 hdr = g_shdr[p0 + lane];
    int e = hdr.y & 0x3FFFF;
    float4 shq = __ldg(&((const float4*)esh)[e]);
    float4 rq0 = __ldg(&((const float4*)rad)[e * 2]);
    float4 rq1 = __ldg(&((const float4*)rad)[e * 2 + 1]);
    sHY[warp][lane] = make_float4(0.f, shq.y, shq.z, shq.w);

    // run-boundary ballot (uniform across warp)
    int r = (int)(((unsigned)hdr.y) >> 18);
    int rprev = __shfl_up_sync(0xffffffffu, r, 1);
    unsigned bnd = __ballot_sync(0xffffffffu, (lane > 0) && (r != rprev));

    // batched radial MLP: 4 batches x 8 edges; lane = (e_loc = lane>>2, j' = lane&3)
    int el = lane >> 2;
    #pragma unroll
    for (int b = 0; b < 4; b++) {
        int src = b * 8 + el;
        float rk, preA, preB;
        rk = __shfl_sync(0xffffffffu, rq0.x, src); preA = rk * W1a[0]; preB = rk * W1b[0];
        rk = __shfl_sync(0xffffffffu, rq0.y, src); preA = fmaf(rk, W1a[1], preA); preB = fmaf(rk, W1b[1], preB);
        rk = __shfl_sync(0xffffffffu, rq0.z, src); preA = fmaf(rk, W1a[2], preA); preB = fmaf(rk, W1b[2], preB);
        rk = __shfl_sync(0xffffffffu, rq0.w, src); preA = fmaf(rk, W1a[3], preA); preB = fmaf(rk, W1b[3], preB);
        rk = __shfl_sync(0xffffffffu, rq1.x, src); preA = fmaf(rk, W1a[4], preA); preB = fmaf(rk, W1b[4], preB);
        rk = __shfl_sync(0xffffffffu, rq1.y, src); preA = fmaf(rk, W1a[5], preA); preB = fmaf(rk, W1b[5], preB);
        rk = __shfl_sync(0xffffffffu, rq1.z, src); preA = fmaf(rk, W1a[6], preA); preB = fmaf(rk, W1b[6], preB);
        rk = __shfl_sync(0xffffffffu, rq1.w, src); preA = fmaf(rk, W1a[7], preA); preB = fmaf(rk, W1b[7], preB);
        float hA = silu_f(preA * INV_SQRT8);
        float hB = silu_f(preB * INV_SQRT8);
        sHp[warp][b * 32 + lane] = pk2(hA, hB);   // slot = E*4 + j'
    }
    __syncwarp();

    // prime the 6-deep sender-gather ring (MLP=6)
    const float4* upL = (const float4*)g_up + lane;
    float4 ring[6];
    #pragma unroll
    for (int q = 0; q < 6; q++) {
        int snd = __shfl_sync(0xffffffffu, hdr.x, q);
        ring[q] = __ldg(&upL[snd * 32]);
    }

    float aS0 = 0.f, aS1 = 0.f;
    float aV0l = 0.f, aV0h = 0.f, aV1l = 0.f, aV1h = 0.f, aV2l = 0.f, aV2h = 0.f;
    int nflush = 0;

    auto flushTo = [&](int node, bool useRed) {
        float* dst = g_acc + (size_t)node * 256 + lane * 8;
        if (useRed) {
            asm volatile("red.global.add.v4.f32 [%0], {%1,%2,%3,%4};"
                         :: "l"(dst), "f"(aS0), "f"(aS1), "f"(aV0l), "f"(aV0h) : "memory");
            asm volatile("red.global.add.v4.f32 [%0], {%1,%2,%3,%4};"
                         :: "l"(dst + 4), "f"(aV1l), "f"(aV1h), "f"(aV2l), "f"(aV2h) : "memory");
        } else {
            asm volatile("st.global.v4.f32 [%0], {%1,%2,%3,%4};"
                         :: "l"(dst), "f"(aS0), "f"(aS1), "f"(aV0l), "f"(aV0h) : "memory");
            asm volatile("st.global.v4.f32 [%0], {%1,%2,%3,%4};"
                         :: "l"(dst + 4), "f"(aV1l), "f"(aV1h), "f"(aV2l), "f"(aV2h) : "memory");
        }
    };

    const ulonglong2* hp2 = (const ulonglong2*)sHp[warp];

    #pragma unroll
    for (int i = 0; i < 32; i++) {
        if (i > 0 && ((bnd >> i) & 1u)) {
            int node = __shfl_sync(0xffffffffu, r, i - 1);
            flushTo(node, nflush == 0);   // first run may straddle backward -> RED
            nflush++;
            aS0 = aS1 = aV0l = aV0h = aV1l = aV1h = aV2l = aV2h = 0.f;
        }
        float4 u = ring[i % 6];
        if (i < 26) {                     // refill ring with edge i+6's gather
            int snd = __shfl_sync(0xffffffffu, hdr.x, i + 6);
            ring[i % 6] = __ldg(&upL[snd * 32]);
        }
        float4 hy = sHY[warp][i];                    // uniform LDS.128 (y0,y1,y2)
        ulonglong2 v1 = hp2[i * 2];                  // h pairs (0,1),(2,3)
        ulonglong2 v2 = hp2[i * 2 + 1];              // h pairs (4,5),(6,7)

        ull a0 = 0, a1 = 0, a2 = 0, a3 = 0;          // 4 independent chains, depth 4
        a0 = fma2_(v1.x, wp[0][0], a0); a1 = fma2_(v1.x, wp[0][1], a1);
        a2 = fma2_(v1.x, wp[0][2], a2); a3 = fma2_(v1.x, wp[0][3], a3);
        a0 = fma2_(v1.y, wp[1][0], a0); a1 = fma2_(v1.y, wp[1][1], a1);
        a2 = fma2_(v1.y, wp[1][2], a2); a3 = fma2_(v1.y, wp[1][3], a3);
        a0 = fma2_(v2.x, wp[2][0], a0); a1 = fma2_(v2.x, wp[2][1], a1);
        a2 = fma2_(v2.x, wp[2][2], a2); a3 = fma2_(v2.x, wp[2][3], a3);
        a0 = fma2_(v2.y, wp[3][0], a0); a1 = fma2_(v2.y, wp[3][1], a1);
        a2 = fma2_(v2.y, wp[3][2], a2); a3 = fma2_(v2.y, wp[3][3], a3);

        float w0, w1, w2, w3, lo, hi;
        upk2(lo, hi, a0); w0 = lo + hi;
        upk2(lo, hi, a1); w1 = lo + hi;
        upk2(lo, hi, a2); w2 = lo + hi;
        upk2(lo, hi, a3); w3 = lo + hi;

        float dot = u.y * hy.y;
        dot = fmaf(u.z, hy.z, dot);
        dot = fmaf(u.w, hy.w, dot);
        float sst = u.x * w2;

        aS0  = fmaf(u.x, w0, aS0);
        aS1  = fmaf(dot, w3, aS1);
        aV0l = fmaf(u.y, w1, aV0l);  aV0h = fmaf(sst, hy.y, aV0h);
        aV1l = fmaf(u.z, w1, aV1l);  aV1h = fmaf(sst, hy.z, aV1h);
        aV2l = fmaf(u.w, w1, aV2l);  aV2h = fmaf(sst, hy.w, aV2h);
    }
    int lastnode = __shfl_sync(0xffffffffu, r, 31);
    flushTo(lastnode, true);   // last run may straddle forward -> RED
}

// ---------------------------------------------------------------------------
// K5 down-projection + skip + gating: 4 nodes per warp, __ldg weights (packed
// ulonglong2 table), f32x2 accumulation. Re-zeroes g_cnt for the next call.
// ---------------------------------------------------------------------------
__global__ void __launch_bounds__(128)
down_kernel(const float* __restrict__ nf,
            const int* __restrict__ species,
            float* __restrict__ out) {
    __shared__ float4 st[4][4][96];   // [warp][node][0:64 columns | 64:96 nf]
    int t = threadIdx.x, warp = t >> 5, lane = t & 31;
    int gid = blockIdx.x * 128 + t;
    if (gid < N_NODES) g_cnt[gid] = 0;     // restore invariant for next call
    int n0 = blockIdx.x * 16 + warp * 4;

    #pragma unroll
    for (int u = 0; u < 4; u++) {
        int n = n0 + u;
        const float4* a4 = (const float4*)g_acc + (size_t)n * 64;
        float4 qa = a4[lane * 2];
        float4 qb = a4[lane * 2 + 1];
        st[warp][u][lane]      = make_float4(qa.x, qa.z, qb.x, qb.z);  // cols m=lane
        st[warp][u][32 + lane] = make_float4(qa.y, qa.w, qb.y, qb.w);  // cols m=32+lane
        const float* f = nf + (size_t)n * 128;
        st[warp][u][64 + lane] = make_float4(f[lane], f[32 + 3 * lane],
                                             f[33 + 3 * lane], f[34 + 3 * lane]);
    }
    __syncwarp();

    const ulonglong2* wdn = (const ulonglong2*)g_pDn4;   // (w2-pair, wv2-pair)
    ull g01[4] = {0, 0, 0, 0}, gv[4] = {0, 0, 0, 0};
    float g4[4] = {0.f, 0.f, 0.f, 0.f};
    #pragma unroll 4
    for (int m = 0; m < 64; m++) {
        ulonglong2 wd = __ldg(&wdn[m * 32 + lane]);
        float wv, dummy;
        upk2(wv, dummy, wd.y);
        #pragma unroll
        for (int u = 0; u < 4; u++) {
            float4 b = st[warp][u][m];
            g01[u] = fma2_(pk2(b.x, b.x), wd.x, g01[u]);
            gv[u]  = fma2_(pk2(b.y, b.z), wd.y, gv[u]);
            g4[u]  = fmaf(b.w, wv, g4[u]);
        }
    }

    int sp[4];
    #pragma unroll
    for (int u = 0; u < 4; u++) sp[u] = species[n0 + u];

    ull s01[4] = {0, 0, 0, 0}, sv[4] = {0, 0, 0, 0};
    float s4[4] = {0.f, 0.f, 0.f, 0.f};
    #pragma unroll 4
    for (int m = 0; m < 32; m++) {
        #pragma unroll
        for (int u = 0; u < 4; u++) {
            float4 w = __ldg(&g_pSk[sp[u] * 1024 + m * 32 + lane]);
            float4 c = st[warp][u][64 + m];
            s01[u] = fma2_(pk2(c.x, c.x), pk2(w.x, w.y), s01[u]);
            sv[u]  = fma2_(pk2(c.y, c.z), pk2(w.z, w.z), sv[u]);
            s4[u]  = fmaf(c.w, w.z, s4[u]);
        }
    }

    const float A = 0.5f * 0.125f;                 // 0.5 * (2*MUL)^-0.5
    const float B = 0.5f * 0.17677669529663687f;   // 0.5 * MUL^-0.5

    #pragma unroll
    for (int u = 0; u < 4; u++) {
        float G0, G1, H0, H1, S0, S1, T0, T1;
        upk2(G0, G1, g01[u]);
        upk2(H0, H1, gv[u]);
        upk2(S0, S1, s01[u]);
        upk2(T0, T1, sv[u]);
        G0 = G0 * A + S0 * B;
        G1 = G1 * A + S1 * B;
        H0 = H0 * A + T0 * B;
        H1 = H1 * A + T1 * B;
        float H2 = g4[u] * A + s4[u] * B;
        float feat = silu_f(G0);
        float gate = silu_f(G1);
        float* o = out + (size_t)(n0 + u) * 128;
        o[lane] = feat;
        o[32 + lane * 3 + 0] = H0 * gate;
        o[32 + lane * 3 + 1] = H1 * gate;
        o[32 + lane * 3 + 2] = H2 * gate;
    }
}

// ---------------------------------------------------------------------------
extern "C" void kernel_launch(void* const* d_in, const int* in_sizes, int n_in,
                              void* d_out, int out_size) {
    const float* nf  = (const float*)d_in[0];
    const float* esh = (const float*)d_in[1];
    const float* rad = (const float*)d_in[2];
    const float* Wus = (const float*)d_in[3];
    const float* Wuv = (const float*)d_in[4];
    const float* Wr1 = (const float*)d_in[5];
    const float* Wr2 = (const float*)d_in[6];
    const float* Wds = (const float*)d_in[7];
    const float* Wdv = (const float*)d_in[8];
    const float* Wss = (const float*)d_in[9];
    const float* Wsv = (const float*)d_in[10];
    const int* snd  = (const int*)d_in[11];
    const int* rcv  = (const int*)d_in[12];
    const int* spec = (const int*)d_in[13];
    float* out = (float*)d_out;

    prep_kernel<<<2332, 256>>>(nf, Wus, Wuv, Wds, Wdv, Wss, Wsv, rcv);
    scan_kernel<<<64, 256>>>();
    mid_kernel<<<4352, 256>>>(rcv, snd);
    edge_kernel<<<2048, 128>>>(Wr1, Wr2, esh, rad);
    down_kernel<<<1024, 128>>>(nf, spec, out);
}

// round 16
// speedup vs baseline: 1.0706x; 1.0459x over previous
#include <cuda_runtime.h>

#define N_NODES 16384
#define N_EDGES 262144

typedef unsigned long long ull;

// ---------------------------------------------------------------------------
// Static device scratch (no runtime allocation). NOTE: g_cnt is zero at module
// load and re-zeroed by down_kernel at the end of every launch sequence, so
// hist can run in the first kernel without a separate zeroing pass.
// ---------------------------------------------------------------------------
__device__ float  g_up[N_NODES * 128];     // [n][lane][4] = (s1, v1x, v1y, v1z)
__device__ float  g_acc[N_NODES * 256];    // [n][lane][8] = (S0,S1,V0l,V0h,V1l,V1h,V2l,V2h)
__device__ int    g_cnt[N_NODES];
__device__ int    g_cursor[N_NODES];
__device__ int    g_base;
__device__ int2   g_shdr[N_EDGES];         // sorted header: (snd, rcv<<18 | e)
__device__ float4 g_pDn4[2048];            // packed (Wds[m][k], Wds[m][32+k], Wdv, Wdv)
__device__ ulonglong2 g_pSk2[4096];        // pre-packed skip weights: {(ss_a,ss_b),(wv,wv)}

__device__ __forceinline__ float silu_f(float x) {
    return x / (1.0f + __expf(-x));
}

__device__ __forceinline__ ull pk2(float a, float b) {
    ull r; asm("mov.b64 %0, {%1,%2};" : "=l"(r) : "f"(a), "f"(b)); return r;
}
__device__ __forceinline__ void upk2(float& a, float& b, ull v) {
    asm("mov.b64 {%0,%1}, %2;" : "=f"(a), "=f"(b) : "l"(v));
}
__device__ __forceinline__ ull fma2_(ull a, ull b, ull c) {
    ull d; asm("fma.rn.f32x2 %0, %1, %2, %3;" : "=l"(d) : "l"(a), "l"(b), "l"(c)); return d;
}

// ---------------------------------------------------------------------------
// K1 fused: weight packing (blocks 0..27) + receiver histogram (28..283,
// 4 edges/thread) + up-projection (284..2331).
// ---------------------------------------------------------------------------
__global__ void __launch_bounds__(256)
prep_kernel(const float* __restrict__ nf,
            const float* __restrict__ Wus, const float* __restrict__ Wuv,
            const float* __restrict__ Wds, const float* __restrict__ Wdv,
            const float* __restrict__ Wss, const float* __restrict__ Wsv,
            const int* __restrict__ rcv) {
    int b = blockIdx.x;
    int t = threadIdx.x;
    if (b < 28) {                                     // pack down/skip weights
        int g = b * 256 + t;
        if (g == 0) g_base = 0;
        int i = g - 1024;
        if (i >= 0 && i < 2048) {
            int m = i >> 5, k = i & 31;
            float wv = Wdv[i];
            g_pDn4[i] = make_float4(Wds[m * 64 + k], Wds[m * 64 + 32 + k], wv, wv);
        }
        int j = g - 3072;
        if (j >= 0 && j < 4096) {
            int sp = j >> 10, q = j & 1023, m = q >> 5, k = q & 31;
            ulonglong2 v;
            v.x = pk2(Wss[sp * 2048 + m * 64 + k], Wss[sp * 2048 + m * 64 + 32 + k]);
            float wc = Wsv[sp * 1024 + q];
            v.y = pk2(wc, wc);
            g_pSk2[j] = v;
        }
        return;
    }
    if (b < 284) {                                    // receiver histogram x4
        int i = (b - 28) * 256 + t;                   // i in [0, 65536)
        int4 rr = ((const int4*)rcv)[i];
        atomicAdd(&g_cnt[rr.x], 1);
        atomicAdd(&g_cnt[rr.y], 1);
        atomicAdd(&g_cnt[rr.z], 1);
        atomicAdd(&g_cnt[rr.w], 1);
        return;
    }
    // up-projection: 8 nodes per block (warp per node); raw weights -> SMEM
    __shared__ float2 sWu[1024];
    __shared__ float4 sF[8][32];
    for (int i = t; i < 1024; i += 256) sWu[i] = make_float2(Wus[i], Wuv[i]);
    __syncthreads();
    int warp = t >> 5, lane = t & 31;
    int n = (b - 284) * 8 + warp;
    const float* f = nf + (size_t)n * 128;
    sF[warp][lane] = make_float4(f[lane], f[32 + 3 * lane],
                                 f[33 + 3 * lane], f[34 + 3 * lane]);
    __syncwarp();
    float os = 0.f, o0 = 0.f, o1 = 0.f, o2 = 0.f;
    #pragma unroll 8
    for (int m = 0; m < 32; m++) {
        float4 v = sF[warp][m];
        float2 w = sWu[m * 32 + lane];
        os = fmaf(v.x, w.x, os);
        o0 = fmaf(v.y, w.y, o0);
        o1 = fmaf(v.z, w.y, o1);
        o2 = fmaf(v.w, w.y, o2);
    }
    const float S = 0.17677669529663687f;
    ((float4*)g_up)[n * 32 + lane] = make_float4(os * S, o0 * S, o1 * S, o2 * S);
}

// ---------------------------------------------------------------------------
// K2 parallel scan: block-local scan + atomic global base
// ---------------------------------------------------------------------------
__global__ void __launch_bounds__(256) scan_kernel() {
    __shared__ int sWarp[8];
    __shared__ int sBase;
    int t = threadIdx.x;
    int lane = t & 31, warp = t >> 5;
    int n = blockIdx.x * 256 + t;
    int c = g_cnt[n];
    int incl = c;
    #pragma unroll
    for (int o = 1; o < 32; o <<= 1) {
        int v = __shfl_up_sync(0xffffffffu, incl, o);
        if (lane >= o) incl += v;
    }
    if (lane == 31) sWarp[warp] = incl;
    __syncthreads();
    if (t < 8) {
        int v = sWarp[t];
        #pragma unroll
        for (int o = 1; o < 8; o <<= 1) {
            int u = __shfl_up_sync(0xffu, v, o);
            if (t >= o) v += u;
        }
        sWarp[t] = v;
        if (t == 7) sBase = atomicAdd(&g_base, v);
    }
    __syncthreads();
    int warpBase = (warp > 0) ? sWarp[warp - 1] : 0;
    g_cursor[n] = sBase + warpBase + incl - c;
}

// ---------------------------------------------------------------------------
// K3 fused: scatter 4 edges/thread (blocks 0..255) + zero_acc (256..4351).
// ---------------------------------------------------------------------------
__global__ void __launch_bounds__(256)
mid_kernel(const int* __restrict__ receivers, const int* __restrict__ senders) {
    int b = blockIdx.x;
    int t = threadIdx.x;
    if (b < 256) {                                    // 8B-header scatter, x4
        int i = b * 256 + t;
        int4 rr = ((const int4*)receivers)[i];
        int4 ss = ((const int4*)senders)[i];
        int e0 = i * 4;
        int p0 = atomicAdd(&g_cursor[rr.x], 1);
        int p1 = atomicAdd(&g_cursor[rr.y], 1);
        int p2 = atomicAdd(&g_cursor[rr.z], 1);
        int p3 = atomicAdd(&g_cursor[rr.w], 1);
        g_shdr[p0] = make_int2(ss.x, (rr.x << 18) | e0);
        g_shdr[p1] = make_int2(ss.y, (rr.y << 18) | (e0 + 1));
        g_shdr[p2] = make_int2(ss.z, (rr.z << 18) | (e0 + 2));
        g_shdr[p3] = make_int2(ss.w, (rr.w << 18) | (e0 + 3));
        return;
    }
    ((float4*)g_acc)[(b - 256) * 256 + t] = make_float4(0.f, 0.f, 0.f, 0.f);
}

// ---------------------------------------------------------------------------
// K4 edge kernel (proven config: 128 threads, 5 blocks/SM, ring 6).
// Byte-identical to the round-13/15 version.
// ---------------------------------------------------------------------------
__global__ void __launch_bounds__(128, 5)
edge_kernel(const float* __restrict__ W_r1, const float* __restrict__ W_r2,
            const float* __restrict__ esh, const float* __restrict__ rad) {
    __shared__ float4 sHY[4][32];     // per warp: (unused, y0, y1, y2) per edge
    __shared__ ull    sHp[4][128];    // per warp: h pairs, 4 ull per edge
    int t = threadIdx.x, warp = t >> 5, lane = t & 31;
    int p0 = (blockIdx.x * 4 + warp) * 32;

    const float INV_SQRT8 = 0.3535533905932738f;
    const float SC = INV_SQRT8 * 0.25f;          // radial scale * AVG_NEIGH^-0.5
    const float INV_SQRT3 = 0.5773502691896258f;

    ull wp[4][4];
    #pragma unroll
    for (int p = 0; p < 4; p++) {
        #pragma unroll
        for (int c = 0; c < 4; c++) {
            float scc = (c == 3) ? SC * INV_SQRT3 : SC;
            wp[p][c] = pk2(__ldg(&W_r2[(2 * p) * 128 + c * 32 + lane]) * scc,
                           __ldg(&W_r2[(2 * p + 1) * 128 + c * 32 + lane]) * scc);
        }
    }
    int j2 = (lane & 3) * 2;
    float W1a[8], W1b[8];
    #pragma unroll
    for (int k = 0; k < 8; k++) {
        W1a[k] = __ldg(&W_r1[k * 8 + j2]);
        W1b[k] = __ldg(&W_r1[k * 8 + j2 + 1]);
    }

    int2 hdr = g_shdr[p0 + lane];
    int e = hdr.y & 0x3FFFF;
    float4 shq = __ldg(&((const float4*)esh)[e]);
    float4 rq0 = __ldg(&((const float4*)rad)[e * 2]);
    float4 rq1 = __ldg(&((const float4*)rad)[e * 2 + 1]);
    sHY[warp][lane] = make_float4(0.f, shq.y, shq.z, shq.w);

    int r = (int)(((unsigned)hdr.y) >> 18);
    int rprev = __shfl_up_sync(0xffffffffu, r, 1);
    unsigned bnd = __ballot_sync(0xffffffffu, (lane > 0) && (r != rprev));

    int el = lane >> 2;
    #pragma unroll
    for (int b = 0; b < 4; b++) {
        int src = b * 8 + el;
        float rk, preA, preB;
        rk = __shfl_sync(0xffffffffu, rq0.x, src); preA = rk * W1a[0]; preB = rk * W1b[0];
        rk = __shfl_sync(0xffffffffu, rq0.y, src); preA = fmaf(rk, W1a[1], preA); preB = fmaf(rk, W1b[1], preB);
        rk = __shfl_sync(0xffffffffu, rq0.z, src); preA = fmaf(rk, W1a[2], preA); preB = fmaf(rk, W1b[2], preB);
        rk = __shfl_sync(0xffffffffu, rq0.w, src); preA = fmaf(rk, W1a[3], preA); preB = fmaf(rk, W1b[3], preB);
        rk = __shfl_sync(0xffffffffu, rq1.x, src); preA = fmaf(rk, W1a[4], preA); preB = fmaf(rk, W1b[4], preB);
        rk = __shfl_sync(0xffffffffu, rq1.y, src); preA = fmaf(rk, W1a[5], preA); preB = fmaf(rk, W1b[5], preB);
        rk = __shfl_sync(0xffffffffu, rq1.z, src); preA = fmaf(rk, W1a[6], preA); preB = fmaf(rk, W1b[6], preB);
        rk = __shfl_sync(0xffffffffu, rq1.w, src); preA = fmaf(rk, W1a[7], preA); preB = fmaf(rk, W1b[7], preB);
        float hA = silu_f(preA * INV_SQRT8);
        float hB = silu_f(preB * INV_SQRT8);
        sHp[warp][b * 32 + lane] = pk2(hA, hB);
    }
    __syncwarp();

    const float4* upL = (const float4*)g_up + lane;
    float4 ring[6];
    #pragma unroll
    for (int q = 0; q < 6; q++) {
        int snd = __shfl_sync(0xffffffffu, hdr.x, q);
        ring[q] = __ldg(&upL[snd * 32]);
    }

    float aS0 = 0.f, aS1 = 0.f;
    float aV0l = 0.f, aV0h = 0.f, aV1l = 0.f, aV1h = 0.f, aV2l = 0.f, aV2h = 0.f;
    int nflush = 0;

    auto flushTo = [&](int node, bool useRed) {
        float* dst = g_acc + (size_t)node * 256 + lane * 8;
        if (useRed) {
            asm volatile("red.global.add.v4.f32 [%0], {%1,%2,%3,%4};"
                         :: "l"(dst), "f"(aS0), "f"(aS1), "f"(aV0l), "f"(aV0h) : "memory");
            asm volatile("red.global.add.v4.f32 [%0], {%1,%2,%3,%4};"
                         :: "l"(dst + 4), "f"(aV1l), "f"(aV1h), "f"(aV2l), "f"(aV2h) : "memory");
        } else {
            asm volatile("st.global.v4.f32 [%0], {%1,%2,%3,%4};"
                         :: "l"(dst), "f"(aS0), "f"(aS1), "f"(aV0l), "f"(aV0h) : "memory");
            asm volatile("st.global.v4.f32 [%0], {%1,%2,%3,%4};"
                         :: "l"(dst + 4), "f"(aV1l), "f"(aV1h), "f"(aV2l), "f"(aV2h) : "memory");
        }
    };

    const ulonglong2* hp2 = (const ulonglong2*)sHp[warp];

    #pragma unroll
    for (int i = 0; i < 32; i++) {
        if (i > 0 && ((bnd >> i) & 1u)) {
            int node = __shfl_sync(0xffffffffu, r, i - 1);
            flushTo(node, nflush == 0);
            nflush++;
            aS0 = aS1 = aV0l = aV0h = aV1l = aV1h = aV2l = aV2h = 0.f;
        }
        float4 u = ring[i % 6];
        if (i < 26) {
            int snd = __shfl_sync(0xffffffffu, hdr.x, i + 6);
            ring[i % 6] = __ldg(&upL[snd * 32]);
        }
        float4 hy = sHY[warp][i];
        ulonglong2 v1 = hp2[i * 2];
        ulonglong2 v2 = hp2[i * 2 + 1];

        ull a0 = 0, a1 = 0, a2 = 0, a3 = 0;
        a0 = fma2_(v1.x, wp[0][0], a0); a1 = fma2_(v1.x, wp[0][1], a1);
        a2 = fma2_(v1.x, wp[0][2], a2); a3 = fma2_(v1.x, wp[0][3], a3);
        a0 = fma2_(v1.y, wp[1][0], a0); a1 = fma2_(v1.y, wp[1][1], a1);
        a2 = fma2_(v1.y, wp[1][2], a2); a3 = fma2_(v1.y, wp[1][3], a3);
        a0 = fma2_(v2.x, wp[2][0], a0); a1 = fma2_(v2.x, wp[2][1], a1);
        a2 = fma2_(v2.x, wp[2][2], a2); a3 = fma2_(v2.x, wp[2][3], a3);
        a0 = fma2_(v2.y, wp[3][0], a0); a1 = fma2_(v2.y, wp[3][1], a1);
        a2 = fma2_(v2.y, wp[3][2], a2); a3 = fma2_(v2.y, wp[3][3], a3);

        float w0, w1, w2, w3, lo, hi;
        upk2(lo, hi, a0); w0 = lo + hi;
        upk2(lo, hi, a1); w1 = lo + hi;
        upk2(lo, hi, a2); w2 = lo + hi;
        upk2(lo, hi, a3); w3 = lo + hi;

        float dot = u.y * hy.y;
        dot = fmaf(u.z, hy.z, dot);
        dot = fmaf(u.w, hy.w, dot);
        float sst = u.x * w2;

        aS0  = fmaf(u.x, w0, aS0);
        aS1  = fmaf(dot, w3, aS1);
        aV0l = fmaf(u.y, w1, aV0l);  aV0h = fmaf(sst, hy.y, aV0h);
        aV1l = fmaf(u.z, w1, aV1l);  aV1h = fmaf(sst, hy.z, aV1h);
        aV2l = fmaf(u.w, w1, aV2l);  aV2h = fmaf(sst, hy.w, aV2h);
    }
    int lastnode = __shfl_sync(0xffffffffu, r, 31);
    flushTo(lastnode, true);
}

// ---------------------------------------------------------------------------
// K5 down-projection + skip + gating: 4 nodes per warp. SMEM holds PRE-PACKED
// f32x2 operand pairs (packed once at staging, broadcast-read in-loop with
// zero per-iteration movs); skip weights pre-packed in g_pSk2.
// ---------------------------------------------------------------------------
__global__ void __launch_bounds__(128)
down_kernel(const float* __restrict__ nf,
            const int* __restrict__ species,
            float* __restrict__ out) {
    __shared__ ulonglong2 sP[4][4][64];   // per (warp,node,m): {(S,S),(V0,V1)}  16KB
    __shared__ float      sV2[4][4][64];  // V2 per (warp,node,m)                 4KB
    __shared__ ulonglong2 sQ[4][4][32];   // {(s,s),(v0,v1)} for skip             8KB
    __shared__ float      sQw[4][4][32];  // v2 for skip                          2KB
    int t = threadIdx.x, warp = t >> 5, lane = t & 31;
    int gid = blockIdx.x * 128 + t;
    if (gid < N_NODES) g_cnt[gid] = 0;     // restore invariant for next call
    int n0 = blockIdx.x * 16 + warp * 4;

    #pragma unroll
    for (int u = 0; u < 4; u++) {
        int n = n0 + u;
        const float4* a4 = (const float4*)g_acc + (size_t)n * 64;
        float4 qa = a4[lane * 2];
        float4 qb = a4[lane * 2 + 1];
        // column m = lane:      (S,V0,V1,V2) = (qa.x, qa.z, qb.x, qb.z)
        // column m = 32+lane:   (S,V0,V1,V2) = (qa.y, qa.w, qb.y, qb.w)
        ulonglong2 pa; pa.x = pk2(qa.x, qa.x); pa.y = pk2(qa.z, qb.x);
        ulonglong2 pb; pb.x = pk2(qa.y, qa.y); pb.y = pk2(qa.w, qb.y);
        sP[warp][u][lane]      = pa;
        sP[warp][u][32 + lane] = pb;
        sV2[warp][u][lane]      = qb.z;
        sV2[warp][u][32 + lane] = qb.w;
        const float* f = nf + (size_t)n * 128;
        float s  = f[lane];
        float v0 = f[32 + 3 * lane];
        float v1 = f[33 + 3 * lane];
        float v2 = f[34 + 3 * lane];
        ulonglong2 qn; qn.x = pk2(s, s); qn.y = pk2(v0, v1);
        sQ[warp][u][lane] = qn;
        sQw[warp][u][lane] = v2;
    }
    __syncwarp();

    const ulonglong2* wdn = (const ulonglong2*)g_pDn4;   // (w2-pair, wv2-pair)
    ull g01[4] = {0, 0, 0, 0}, gv[4] = {0, 0, 0, 0};
    float g4[4] = {0.f, 0.f, 0.f, 0.f};
    #pragma unroll 4
    for (int m = 0; m < 64; m++) {
        ulonglong2 wd = __ldg(&wdn[m * 32 + lane]);
        float wv, d_;
        upk2(wv, d_, wd.y);
        #pragma unroll
        for (int u = 0; u < 4; u++) {
            ulonglong2 p = sP[warp][u][m];           // uniform LDS.128, pre-packed
            float v2 = sV2[warp][u][m];              // uniform LDS.32
            g01[u] = fma2_(p.x, wd.x, g01[u]);
            gv[u]  = fma2_(p.y, wd.y, gv[u]);
            g4[u]  = fmaf(v2, wv, g4[u]);
        }
    }

    int sp[4];
    #pragma unroll
    for (int u = 0; u < 4; u++) sp[u] = species[n0 + u];

    ull s01[4] = {0, 0, 0, 0}, sv[4] = {0, 0, 0, 0};
    float s4[4] = {0.f, 0.f, 0.f, 0.f};
    #pragma unroll 4
    for (int m = 0; m < 32; m++) {
        #pragma unroll
        for (int u = 0; u < 4; u++) {
            ulonglong2 w = __ldg(&g_pSk2[sp[u] * 1024 + m * 32 + lane]);  // pre-packed
            ulonglong2 q = sQ[warp][u][m];           // uniform LDS.128, pre-packed
            float v2 = sQw[warp][u][m];
            s01[u] = fma2_(q.x, w.x, s01[u]);
            sv[u]  = fma2_(q.y, w.y, sv[u]);
            float wc, d2;
            upk2(wc, d2, w.y);
            s4[u]  = fmaf(v2, wc, s4[u]);
        }
    }

    const float A = 0.5f * 0.125f;                 // 0.5 * (2*MUL)^-0.5
    const float B = 0.5f * 0.17677669529663687f;   // 0.5 * MUL^-0.5

    #pragma unroll
    for (int u = 0; u < 4; u++) {
        float G0, G1, H0, H1, S0, S1, T0, T1;
        upk2(G0, G1, g01[u]);
        upk2(H0, H1, gv[u]);
        upk2(S0, S1, s01[u]);
        upk2(T0, T1, sv[u]);
        G0 = G0 * A + S0 * B;
        G1 = G1 * A + S1 * B;
        H0 = H0 * A + T0 * B;
        H1 = H1 * A + T1 * B;
        float H2 = g4[u] * A + s4[u] * B;
        float feat = silu_f(G0);
        float gate = silu_f(G1);
        float* o = out + (size_t)(n0 + u) * 128;
        o[lane] = feat;
        o[32 + lane * 3 + 0] = H0 * gate;
        o[32 + lane * 3 + 1] = H1 * gate;
        o[32 + lane * 3 + 2] = H2 * gate;
    }
}

// ---------------------------------------------------------------------------
extern "C" void kernel_launch(void* const* d_in, const int* in_sizes, int n_in,
                              void* d_out, int out_size) {
    const float* nf  = (const float*)d_in[0];
    const float* esh = (const float*)d_in[1];
    const float* rad = (const float*)d_in[2];
    const float* Wus = (const float*)d_in[3];
    const float* Wuv = (const float*)d_in[4];
    const float* Wr1 = (const float*)d_in[5];
    const float* Wr2 = (const float*)d_in[6];
    const float* Wds = (const float*)d_in[7];
    const float* Wdv = (const float*)d_in[8];
    const float* Wss = (const float*)d_in[9];
    const float* Wsv = (const float*)d_in[10];
    const int* snd  = (const int*)d_in[11];
    const int* rcv  = (const int*)d_in[12];
    const int* spec = (const int*)d_in[13];
    float* out = (float*)d_out;

    prep_kernel<<<2332, 256>>>(nf, Wus, Wuv, Wds, Wdv, Wss, Wsv, rcv);
    scan_kernel<<<64, 256>>>();
    mid_kernel<<<4352, 256>>>(rcv, snd);
    edge_kernel<<<2048, 128>>>(Wr1, Wr2, esh, rad);
    down_kernel<<<1024, 128>>>(nf, spec, out);
}